// round 11
// baseline (speedup 1.0000x reference)
#include <cuda_runtime.h>
#include <cuda_bf16.h>
#include <mma.h>
#include <math.h>
#include <stdint.h>

using namespace nvcuda;

#define NSEQ 1024
#define DMOD 512
#define NHEAD 16
#define HDIM 32
#define DZ 128
#define NN (NSEQ*NSEQ)
#define QSCALE 0.17677669529663687f

typedef unsigned long long u64;
typedef __nv_bfloat16 bf16;

__device__ float g_q[NHEAD*NSEQ*HDIM];
__device__ float g_k[NHEAD*NSEQ*HDIM];
__device__ float g_v[NHEAD*NSEQ*HDIM];
__device__ float g_gate[NSEQ*DMOD];
__device__ float g_o[NSEQ*DMOD];
__device__ float g_scores[NHEAD*NN];
__device__ float g_wzp[DZ*NHEAD];
__device__ float g_alpha[NHEAD];
__device__ float g_beta[NHEAD];
__device__ bf16 g_sa_hi[NSEQ*DMOD], g_sa_lo[NSEQ*DMOD];
__device__ bf16 g_oa_hi[NSEQ*DMOD], g_oa_lo[NSEQ*DMOD];
__device__ bf16 g_wt_hi[5*DMOD*DMOD], g_wt_lo[5*DMOD*DMOD];

__device__ __forceinline__ uint32_t s2u(const void* p) {
    uint32_t a;
    asm("{ .reg .u64 t; cvta.to.shared.u64 t, %1; cvt.u32.u64 %0, t; }" : "=r"(a) : "l"(p));
    return a;
}
__device__ __forceinline__ void cp16(void* smem, const void* g) {
    asm volatile("cp.async.cg.shared.global [%0], [%1], 16;"
                 :: "r"(s2u(smem)), "l"(g) : "memory");
}
__device__ __forceinline__ void cp_commit() {
    asm volatile("cp.async.commit_group;" ::: "memory");
}

__global__ void prep_kernel(const float* __restrict__ Wz,
                            const float* __restrict__ zw,
                            const float* __restrict__ zb)
{
    int t = threadIdx.x;
    for (int i = t; i < DZ*NHEAD; i += blockDim.x)
        g_wzp[i] = zw[i >> 4] * Wz[i];
    if (t < NHEAD) {
        float a = 0.f, b = 0.f;
        for (int c = 0; c < DZ; c++) {
            float wv = Wz[c*NHEAD + t];
            a += zw[c] * wv;
            b += zb[c] * wv;
        }
        g_alpha[t] = a;
        g_beta[t]  = b;
    }
}

__global__ __launch_bounds__(128) void ln_s_kernel(const float* __restrict__ s,
                                                   const float* __restrict__ w,
                                                   const float* __restrict__ b)
{
    __shared__ float sred[8];
    __shared__ float s_mu, s_rstd;
    int row = blockIdx.x, tid = threadIdx.x;
    float4 v = *(const float4*)&s[row*DMOD + tid*4];
    float sum = v.x + v.y + v.z + v.w;
    float ssq = v.x*v.x + v.y*v.y + v.z*v.z + v.w*v.w;
    #pragma unroll
    for (int o = 16; o; o >>= 1) {
        sum += __shfl_xor_sync(0xffffffffu, sum, o);
        ssq += __shfl_xor_sync(0xffffffffu, ssq, o);
    }
    int lane = tid & 31, wid = tid >> 5;
    if (lane == 0) { sred[wid] = sum; sred[4 + wid] = ssq; }
    __syncthreads();
    if (tid == 0) {
        float a = sred[0]+sred[1]+sred[2]+sred[3];
        float q = sred[4]+sred[5]+sred[6]+sred[7];
        float mu = a * (1.f/DMOD);
        float var = q * (1.f/DMOD) - mu*mu;
        s_mu = mu; s_rstd = rsqrtf(var + 1e-5f);
    }
    __syncthreads();
    float mu = s_mu, rstd = s_rstd;
    float4 wv = *(const float4*)&w[tid*4];
    float4 bv = *(const float4*)&b[tid*4];
    float o4[4];
    o4[0] = (v.x-mu)*rstd*wv.x + bv.x;
    o4[1] = (v.y-mu)*rstd*wv.y + bv.y;
    o4[2] = (v.z-mu)*rstd*wv.z + bv.z;
    o4[3] = (v.w-mu)*rstd*wv.w + bv.w;
    union { bf16 h[4]; uint2 u; } H, L;
    #pragma unroll
    for (int j = 0; j < 4; j++) {
        H.h[j] = __float2bfloat16(o4[j]);
        L.h[j] = __float2bfloat16(o4[j] - __bfloat162float(H.h[j]));
    }
    int idx = row*DMOD + tid*4;
    *(uint2*)&g_sa_hi[idx] = H.u;
    *(uint2*)&g_sa_lo[idx] = L.u;
}

__global__ void wtrans_kernel(const float* __restrict__ Wq, const float* __restrict__ Wk,
                              const float* __restrict__ Wv, const float* __restrict__ Wg,
                              const float* __restrict__ Wo)
{
    __shared__ float t[32][33];
    int g = blockIdx.z;
    const float* W = (g==0)?Wq:(g==1)?Wk:(g==2)?Wv:(g==3)?Wg:Wo;
    int tx = threadIdx.x, ty = threadIdx.y;
    int bx = blockIdx.x*32, by = blockIdx.y*32;
    #pragma unroll
    for (int i = 0; i < 4; i++)
        t[ty + 8*i][tx] = W[(size_t)(by + ty + 8*i)*DMOD + bx + tx];
    __syncthreads();
    size_t base = (size_t)g*DMOD*DMOD;
    #pragma unroll
    for (int i = 0; i < 4; i++) {
        int n = bx + ty + 8*i, k = by + tx;
        float v = t[tx][ty + 8*i];
        bf16 h = __float2bfloat16(v);
        g_wt_hi[base + (size_t)n*DMOD + k] = h;
        g_wt_lo[base + (size_t)n*DMOD + k] = __float2bfloat16(v - __bfloat162float(h));
    }
}

__global__ __launch_bounds__(256) void conv_o_kernel()
{
    int idx = (blockIdx.x*256 + threadIdx.x)*4;
    float4 o = *(const float4*)&g_o[idx];
    float4 g = *(const float4*)&g_gate[idx];
    float v[4] = {o.x*g.x, o.y*g.y, o.z*g.z, o.w*g.w};
    union { bf16 h[4]; uint2 u; } H, L;
    #pragma unroll
    for (int j = 0; j < 4; j++) {
        H.h[j] = __float2bfloat16(v[j]);
        L.h[j] = __float2bfloat16(v[j] - __bfloat162float(H.h[j]));
    }
    *(uint2*)&g_oa_hi[idx] = H.u;
    *(uint2*)&g_oa_lo[idx] = L.u;
}

// WMMA bf16-split GEMM with 2-stage cp.async pipeline (R10, unchanged).
__global__ __launch_bounds__(256) void tc_gemm(const float* __restrict__ bq,
                                               float* __restrict__ Cout, int mode_sel)
{
    extern __shared__ __align__(16) char dynsm[];
    const int STAGE = 64*72*2;
    float* Cs = (float*)dynsm;

    int mode = (mode_sel < 0) ? (int)blockIdx.z : mode_sel;
    const bf16* Ah = (mode==4) ? g_oa_hi : g_sa_hi;
    const bf16* Al = (mode==4) ? g_oa_lo : g_sa_lo;
    size_t wb = (size_t)((mode==4)?4:mode)*DMOD*DMOD;
    const bf16* Bh = g_wt_hi + wb;
    const bf16* Bl = g_wt_lo + wb;

    int tid = threadIdx.x;
    int w = tid >> 5, wr = w >> 1, wc = w & 1;
    int m0 = blockIdx.y*64, n0 = blockIdx.x*64;
    int lrow = tid >> 2, lseg = (tid & 3) << 4;

    wmma::fragment<wmma::accumulator,16,16,16,float> acc[2];
    wmma::fill_fragment(acc[0], 0.f);
    wmma::fill_fragment(acc[1], 0.f);

    const bf16* gAh = Ah + (size_t)(m0+lrow)*DMOD + lseg;
    const bf16* gAl = Al + (size_t)(m0+lrow)*DMOD + lseg;
    const bf16* gBh = Bh + (size_t)(n0+lrow)*DMOD + lseg;
    const bf16* gBl = Bl + (size_t)(n0+lrow)*DMOD + lseg;
    int soff = (lrow*72 + lseg)*2;

    auto issue = [&](int ch, int st) {
        char* base = dynsm + st*4*STAGE;
        cp16(base + 0*STAGE + soff,      gAh + ch*64);
        cp16(base + 0*STAGE + soff + 16, gAh + ch*64 + 8);
        cp16(base + 1*STAGE + soff,      gAl + ch*64);
        cp16(base + 1*STAGE + soff + 16, gAl + ch*64 + 8);
        cp16(base + 2*STAGE + soff,      gBh + ch*64);
        cp16(base + 2*STAGE + soff + 16, gBh + ch*64 + 8);
        cp16(base + 3*STAGE + soff,      gBl + ch*64);
        cp16(base + 3*STAGE + soff + 16, gBl + ch*64 + 8);
        cp_commit();
    };

    issue(0, 0);
    for (int ch = 0; ch < 8; ch++) {
        int st = ch & 1;
        if (ch < 7) issue(ch+1, st^1);
        if (ch < 7) asm volatile("cp.async.wait_group 1;" ::: "memory");
        else        asm volatile("cp.async.wait_group 0;" ::: "memory");
        __syncthreads();
        bf16* Ah_s = (bf16*)(dynsm + st*4*STAGE + 0*STAGE);
        bf16* Al_s = (bf16*)(dynsm + st*4*STAGE + 1*STAGE);
        bf16* Bh_s = (bf16*)(dynsm + st*4*STAGE + 2*STAGE);
        bf16* Bl_s = (bf16*)(dynsm + st*4*STAGE + 3*STAGE);
        #pragma unroll
        for (int ks = 0; ks < 4; ks++) {
            wmma::fragment<wmma::matrix_a,16,16,16,bf16,wmma::row_major> fah, fal;
            wmma::load_matrix_sync(fah, Ah_s + (wr*16)*72 + ks*16, 72);
            wmma::load_matrix_sync(fal, Al_s + (wr*16)*72 + ks*16, 72);
            #pragma unroll
            for (int c = 0; c < 2; c++) {
                wmma::fragment<wmma::matrix_b,16,16,16,bf16,wmma::col_major> fbh, fbl;
                wmma::load_matrix_sync(fbh, Bh_s + (wc*32 + c*16)*72 + ks*16, 72);
                wmma::load_matrix_sync(fbl, Bl_s + (wc*32 + c*16)*72 + ks*16, 72);
                wmma::mma_sync(acc[c], fah, fbh, acc[c]);
                wmma::mma_sync(acc[c], fah, fbl, acc[c]);
                wmma::mma_sync(acc[c], fal, fbh, acc[c]);
            }
        }
        __syncthreads();
    }
    wmma::store_matrix_sync(Cs + (wr*16)*72 + wc*32,      acc[0], 72, wmma::mem_row_major);
    wmma::store_matrix_sync(Cs + (wr*16)*72 + wc*32 + 16, acc[1], 72, wmma::mem_row_major);
    __syncthreads();

    int r = lrow;
    int colg = n0 + lseg;
    if (mode <= 2) {
        float* dst = (mode==0) ? g_q : (mode==1 ? g_k : g_v);
        float* dp = &dst[((size_t)(colg >> 5)*NSEQ + m0 + r)*HDIM + (colg & 31)];
        #pragma unroll
        for (int j = 0; j < 4; j++) {
            float4 v = *(float4*)&Cs[r*72 + lseg + j*4];
            if (mode == 0) {
                float4 bb = *(const float4*)&bq[colg + j*4];
                v.x = (v.x + bb.x)*QSCALE; v.y = (v.y + bb.y)*QSCALE;
                v.z = (v.z + bb.z)*QSCALE; v.w = (v.w + bb.w)*QSCALE;
            }
            *(float4*)&dp[j*4] = v;
        }
    } else if (mode == 3) {
        float* dp = &g_gate[(size_t)(m0 + r)*DMOD + colg];
        #pragma unroll
        for (int j = 0; j < 4; j++) {
            float4 v = *(float4*)&Cs[r*72 + lseg + j*4];
            v.x = 1.f/(1.f + __expf(-v.x)); v.y = 1.f/(1.f + __expf(-v.y));
            v.z = 1.f/(1.f + __expf(-v.z)); v.w = 1.f/(1.f + __expf(-v.w));
            *(float4*)&dp[j*4] = v;
        }
    } else {
        float* dp = &Cout[(size_t)(m0 + r)*DMOD + colg];
        #pragma unroll
        for (int j = 0; j < 4; j++)
            *(float4*)&dp[j*4] = *(float4*)&Cs[r*72 + lseg + j*4];
    }
}

// fused LN(z)@Wz v4: cp.async streaming. CTA = 128-row x 128-col tile (full DZ).
// 4 row-groups of 32 double-buffered; split to bf16 hi/lo; per-row stats via
// warp xor-reduce (row r of a group lives entirely in warp r&7... by construction
// warp w handles rows w, w+8, w+16, w+24 of each group); 24 HMMA per warp.
// smem layout (dynamic, 111616 B -> 2 CTA/SM):
//   [0, 32768)        fp32 staging [2][32][128]   (reused as C [8][16][20] later)
//   [32768, 67584)    zh [128][136] bf16
//   [67584, 102400)   zl [128][136] bf16
//   [102400, 106496)  wzh [128][16] bf16
//   [106496, 110592)  wzl [128][16] bf16
//   [110592, 111616)  sum_s[128], ssq_s[128]
__global__ __launch_bounds__(256) void zbias_kernel(const float* __restrict__ z)
{
    extern __shared__ __align__(16) char zsm[];
    float* stage = (float*)zsm;
    bf16*  zh    = (bf16*)(zsm + 32768);
    bf16*  zl    = (bf16*)(zsm + 67584);
    bf16*  wzh   = (bf16*)(zsm + 102400);
    bf16*  wzl   = (bf16*)(zsm + 106496);
    float* sum_s = (float*)(zsm + 110592);
    float* ssq_s = sum_s + 128;

    int tid = threadIdx.x, lane = tid & 31, wid = tid >> 5;

    for (int i = tid; i < DZ*NHEAD; i += 256) {
        float v = g_wzp[i];
        bf16 h = __float2bfloat16(v);
        wzh[i] = h;
        wzl[i] = __float2bfloat16(v - __bfloat162float(h));
    }

    size_t row0 = (size_t)blockIdx.x * 128;
    const float* zg = z + row0*DZ;

    auto issue = [&](int g) {
        float* buf = stage + (g & 1)*32*128;
        const float* src = zg + (size_t)g*32*128;
        #pragma unroll
        for (int j = 0; j < 4; j++) {
            int idx = tid + 256*j;
            cp16(buf + idx*4, src + idx*4);
        }
        cp_commit();
    };
    issue(0);
    issue(1);

    for (int g = 0; g < 4; g++) {
        if (g < 3) asm volatile("cp.async.wait_group 1;" ::: "memory");
        else       asm volatile("cp.async.wait_group 0;" ::: "memory");
        __syncthreads();
        float* buf = stage + (g & 1)*32*128;
        float sums[4], ssqs[4];
        #pragma unroll
        for (int k = 0; k < 4; k++) {
            int r = wid + 8*k;                 // local row in group (warp-owned)
            float4 v = *(const float4*)&buf[r*128 + lane*4];
            int grow = g*32 + r;               // row in 128-row tile
            union { bf16 h[4]; uint2 u; } H, L;
            float vr[4] = {v.x, v.y, v.z, v.w};
            float s_ = 0.f, q_ = 0.f;
            #pragma unroll
            for (int e = 0; e < 4; e++) {
                H.h[e] = __float2bfloat16(vr[e]);
                L.h[e] = __float2bfloat16(vr[e] - __bfloat162float(H.h[e]));
                s_ += vr[e];
                q_ = fmaf(vr[e], vr[e], q_);
            }
            *(uint2*)&zh[grow*136 + lane*4] = H.u;
            *(uint2*)&zl[grow*136 + lane*4] = L.u;
            sums[k] = s_; ssqs[k] = q_;
        }
        #pragma unroll
        for (int k = 0; k < 4; k++) {
            #pragma unroll
            for (int o = 16; o; o >>= 1) {
                sums[k] += __shfl_xor_sync(0xffffffffu, sums[k], o);
                ssqs[k] += __shfl_xor_sync(0xffffffffu, ssqs[k], o);
            }
        }
        if (lane == 0) {
            #pragma unroll
            for (int k = 0; k < 4; k++) {
                sum_s[g*32 + wid + 8*k] = sums[k];
                ssq_s[g*32 + wid + 8*k] = ssqs[k];
            }
        }
        __syncthreads();          // all reads of buf done before reissue
        if (g < 2) issue(g + 2);
    }

    // MMA: warp w owns rows 16w..16w+15; full K=128 in 8 ksteps, 3-way split.
    wmma::fragment<wmma::accumulator,16,16,16,float> accf;
    wmma::fill_fragment(accf, 0.f);
    #pragma unroll
    for (int ks = 0; ks < 8; ks++) {
        wmma::fragment<wmma::matrix_a,16,16,16,bf16,wmma::row_major> fah, fal;
        wmma::fragment<wmma::matrix_b,16,16,16,bf16,wmma::row_major> fbh, fbl;
        wmma::load_matrix_sync(fah, zh + (wid*16)*136 + ks*16, 136);
        wmma::load_matrix_sync(fal, zl + (wid*16)*136 + ks*16, 136);
        wmma::load_matrix_sync(fbh, wzh + ks*16*16, 16);
        wmma::load_matrix_sync(fbl, wzl + ks*16*16, 16);
        wmma::mma_sync(accf, fah, fbh, accf);
        wmma::mma_sync(accf, fah, fbl, accf);
        wmma::mma_sync(accf, fal, fbh, accf);
    }
    __syncthreads();              // stage free for C
    float* C = stage + wid*16*20;
    wmma::store_matrix_sync(C, accf, 20, wmma::mem_row_major);
    __syncthreads();

    int r = tid >> 1, h0 = (tid & 1)*8;
    const float* Cr = stage + (r >> 4)*16*20 + (r & 15)*20;
    float mu = sum_s[r] * (1.f/DZ);
    float var = ssq_s[r] * (1.f/DZ) - mu*mu;
    float rstd = rsqrtf(var + 1e-5f);
    size_t row = row0 + r;
    #pragma unroll
    for (int j = 0; j < 8; j++) {
        int h = h0 + j;
        g_scores[(size_t)h*NN + row] = rstd*(Cr[h] - mu*g_alpha[h]) + g_beta[h];
    }
}

// Flash attention (R10, unchanged).
__global__ __launch_bounds__(256) void flash_kernel()
{
    __shared__ float Qs[32][68];
    __shared__ float Ks[32][68];
    __shared__ float Vs[64][36];
    __shared__ float Ps[64][68];
    __shared__ float corr_s[64];
    __shared__ float l_s[64];
    int tid = threadIdx.x;
    int h = blockIdx.y, q0 = blockIdx.x*64;
    const float* qb = g_q + h*NSEQ*HDIM;
    const float* kp = g_k + h*NSEQ*HDIM;
    const float* vp = g_v + h*NSEQ*HDIM;
    const float* zp = g_scores + (size_t)h*NN;

    int lr = tid >> 2;
    int lc = (tid & 3) << 2;
    {
        float4 a = *(const float4*)&qb[(q0+lr)*HDIM + lc];
        float4 b = *(const float4*)&qb[(q0+lr)*HDIM + lc + 16];
        Qs[lc+0][lr]=a.x; Qs[lc+1][lr]=a.y; Qs[lc+2][lr]=a.z; Qs[lc+3][lr]=a.w;
        Qs[lc+16][lr]=b.x; Qs[lc+17][lr]=b.y; Qs[lc+18][lr]=b.z; Qs[lc+19][lr]=b.w;
    }
    int tx = tid & 15, ty = tid >> 4;
    int oty = tid >> 3, otx = tid & 7;
    int vc = (tid & 3) << 3;
    float m[4], l[4];
    #pragma unroll
    for (int i = 0; i < 4; i++) { m[i] = -1e30f; l[i] = 0.f; }
    float oacc[2][4] = {};

    for (int kb0 = 0; kb0 < NSEQ; kb0 += 64) {
        float4 ka = *(const float4*)&kp[(kb0+lr)*HDIM + lc];
        float4 kc2 = *(const float4*)&kp[(kb0+lr)*HDIM + lc + 16];
        float4 v0 = *(const float4*)&vp[(kb0+lr)*HDIM + vc];
        float4 v1 = *(const float4*)&vp[(kb0+lr)*HDIM + vc + 4];
        __syncthreads();
        Ks[lc+0][lr]=ka.x; Ks[lc+1][lr]=ka.y; Ks[lc+2][lr]=ka.z; Ks[lc+3][lr]=ka.w;
        Ks[lc+16][lr]=kc2.x; Ks[lc+17][lr]=kc2.y; Ks[lc+18][lr]=kc2.z; Ks[lc+19][lr]=kc2.w;
        *(float4*)&Vs[lr][vc] = v0;
        *(float4*)&Vs[lr][vc+4] = v1;
        __syncthreads();

        float s[4][4];
        #pragma unroll
        for (int i = 0; i < 4; i++) {
            float4 z4 = *(const float4*)&zp[(size_t)(q0+(ty<<2)+i)*NSEQ + kb0 + (tx<<2)];
            s[i][0]=z4.x; s[i][1]=z4.y; s[i][2]=z4.z; s[i][3]=z4.w;
        }
        #pragma unroll
        for (int kk = 0; kk < 32; kk++) {
            float4 a4 = *(const float4*)&Qs[kk][ty << 2];
            float4 b4 = *(const float4*)&Ks[kk][tx << 2];
            float ar[4] = {a4.x,a4.y,a4.z,a4.w};
            float br[4] = {b4.x,b4.y,b4.z,b4.w};
            #pragma unroll
            for (int i = 0; i < 4; i++)
                #pragma unroll
                for (int j = 0; j < 4; j++)
                    s[i][j] = fmaf(ar[i], br[j], s[i][j]);
        }
        #pragma unroll
        for (int i = 0; i < 4; i++) {
            float mx = fmaxf(fmaxf(s[i][0],s[i][1]), fmaxf(s[i][2],s[i][3]));
            mx = fmaxf(mx, __shfl_xor_sync(0xffffffffu, mx, 1));
            mx = fmaxf(mx, __shfl_xor_sync(0xffffffffu, mx, 2));
            mx = fmaxf(mx, __shfl_xor_sync(0xffffffffu, mx, 4));
            mx = fmaxf(mx, __shfl_xor_sync(0xffffffffu, mx, 8));
            float mnew = fmaxf(m[i], mx);
            float c = __expf(m[i] - mnew);
            s[i][0] = __expf(s[i][0]-mnew); s[i][1] = __expf(s[i][1]-mnew);
            s[i][2] = __expf(s[i][2]-mnew); s[i][3] = __expf(s[i][3]-mnew);
            float rs = s[i][0]+s[i][1]+s[i][2]+s[i][3];
            rs += __shfl_xor_sync(0xffffffffu, rs, 1);
            rs += __shfl_xor_sync(0xffffffffu, rs, 2);
            rs += __shfl_xor_sync(0xffffffffu, rs, 4);
            rs += __shfl_xor_sync(0xffffffffu, rs, 8);
            l[i] = l[i]*c + rs;
            m[i] = mnew;
            int row = (ty << 2) + i;
            if (tx == 0) { corr_s[row] = c; l_s[row] = l[i]; }
            *(float4*)&Ps[row][tx << 2] = make_float4(s[i][0],s[i][1],s[i][2],s[i][3]);
        }
        __syncthreads();

        float c0 = corr_s[oty*2], c1 = corr_s[oty*2+1];
        #pragma unroll
        for (int j = 0; j < 4; j++) { oacc[0][j] *= c0; oacc[1][j] *= c1; }
        #pragma unroll
        for (int kk = 0; kk < 64; kk++) {
            float p0 = Ps[oty*2][kk];
            float p1 = Ps[oty*2+1][kk];
            float4 vv = *(const float4*)&Vs[kk][otx << 2];
            oacc[0][0]=fmaf(p0,vv.x,oacc[0][0]); oacc[0][1]=fmaf(p0,vv.y,oacc[0][1]);
            oacc[0][2]=fmaf(p0,vv.z,oacc[0][2]); oacc[0][3]=fmaf(p0,vv.w,oacc[0][3]);
            oacc[1][0]=fmaf(p1,vv.x,oacc[1][0]); oacc[1][1]=fmaf(p1,vv.y,oacc[1][1]);
            oacc[1][2]=fmaf(p1,vv.z,oacc[1][2]); oacc[1][3]=fmaf(p1,vv.w,oacc[1][3]);
        }
    }
    float inv0 = 1.f / l_s[oty*2];
    float inv1 = 1.f / l_s[oty*2+1];
    *(float4*)&g_o[(q0 + oty*2 + 0)*DMOD + h*HDIM + (otx << 2)] =
        make_float4(oacc[0][0]*inv0, oacc[0][1]*inv0, oacc[0][2]*inv0, oacc[0][3]*inv0);
    *(float4*)&g_o[(q0 + oty*2 + 1)*DMOD + h*HDIM + (otx << 2)] =
        make_float4(oacc[1][0]*inv1, oacc[1][1]*inv1, oacc[1][2]*inv1, oacc[1][3]*inv1);
}

extern "C" void kernel_launch(void* const* d_in, const int* in_sizes, int n_in,
                              void* d_out, int out_size)
{
    const float* s   = (const float*)d_in[0];
    const float* z   = (const float*)d_in[1];
    const float* nsw = (const float*)d_in[2];
    const float* nsb = (const float*)d_in[3];
    const float* Wq  = (const float*)d_in[4];
    const float* bq  = (const float*)d_in[5];
    const float* Wk  = (const float*)d_in[6];
    const float* Wv  = (const float*)d_in[7];
    const float* Wg  = (const float*)d_in[8];
    const float* zw  = (const float*)d_in[9];
    const float* zb  = (const float*)d_in[10];
    const float* Wz  = (const float*)d_in[11];
    const float* Wo  = (const float*)d_in[12];
    float* out = (float*)d_out;

    cudaFuncSetAttribute(tc_gemm, cudaFuncAttributeMaxDynamicSharedMemorySize, 73728);
    cudaFuncSetAttribute(zbias_kernel, cudaFuncAttributeMaxDynamicSharedMemorySize, 111616);

    prep_kernel<<<1, 256>>>(Wz, zw, zb);
    ln_s_kernel<<<NSEQ, 128>>>(s, nsw, nsb);
    wtrans_kernel<<<dim3(16,16,5), dim3(32,8)>>>(Wq, Wk, Wv, Wg, Wo);
    tc_gemm<<<dim3(8,16,4), 256, 73728>>>(bq, nullptr, -1);
    zbias_kernel<<<NN/128, 256, 111616>>>(z);
    flash_kernel<<<dim3(NSEQ/64, NHEAD), 256>>>();
    conv_o_kernel<<<NSEQ*DMOD/4/256, 256>>>();
    tc_gemm<<<dim3(8,16,1), 256, 73728>>>(bq, out, 4);
}

// round 12
// speedup vs baseline: 1.3317x; 1.3317x over previous
#include <cuda_runtime.h>
#include <cuda_bf16.h>
#include <mma.h>
#include <math.h>
#include <stdint.h>

using namespace nvcuda;

#define NSEQ 1024
#define DMOD 512
#define NHEAD 16
#define HDIM 32
#define DZ 128
#define NN (NSEQ*NSEQ)
#define QSCALE 0.17677669529663687f

typedef unsigned long long u64;
typedef __nv_bfloat16 bf16;

__device__ float g_gate[NSEQ*DMOD];
__device__ float g_o[NSEQ*DMOD];
__device__ float g_scores[NHEAD*NN];
__device__ float g_wzp[DZ*NHEAD];
__device__ float g_alpha[NHEAD];
__device__ float g_beta[NHEAD];
__device__ bf16 g_sa_hi[NSEQ*DMOD], g_sa_lo[NSEQ*DMOD];
__device__ bf16 g_oa_hi[NSEQ*DMOD], g_oa_lo[NSEQ*DMOD];
__device__ bf16 g_wt_hi[5*DMOD*DMOD], g_wt_lo[5*DMOD*DMOD];
__device__ bf16 g_qh[NHEAD*NSEQ*HDIM], g_ql[NHEAD*NSEQ*HDIM];
__device__ bf16 g_kh[NHEAD*NSEQ*HDIM], g_kl[NHEAD*NSEQ*HDIM];
__device__ bf16 g_vh[NHEAD*NSEQ*HDIM], g_vl[NHEAD*NSEQ*HDIM];

__device__ __forceinline__ uint32_t s2u(const void* p) {
    uint32_t a;
    asm("{ .reg .u64 t; cvta.to.shared.u64 t, %1; cvt.u32.u64 %0, t; }" : "=r"(a) : "l"(p));
    return a;
}
__device__ __forceinline__ void cp16(void* smem, const void* g) {
    asm volatile("cp.async.cg.shared.global [%0], [%1], 16;"
                 :: "r"(s2u(smem)), "l"(g) : "memory");
}
__device__ __forceinline__ void cp_commit() {
    asm volatile("cp.async.commit_group;" ::: "memory");
}

__global__ void prep_kernel(const float* __restrict__ Wz,
                            const float* __restrict__ zw,
                            const float* __restrict__ zb)
{
    int t = threadIdx.x;
    for (int i = t; i < DZ*NHEAD; i += blockDim.x)
        g_wzp[i] = zw[i >> 4] * Wz[i];
    if (t < NHEAD) {
        float a = 0.f, b = 0.f;
        for (int c = 0; c < DZ; c++) {
            float wv = Wz[c*NHEAD + t];
            a += zw[c] * wv;
            b += zb[c] * wv;
        }
        g_alpha[t] = a;
        g_beta[t]  = b;
    }
}

__global__ __launch_bounds__(128) void ln_s_kernel(const float* __restrict__ s,
                                                   const float* __restrict__ w,
                                                   const float* __restrict__ b)
{
    __shared__ float sred[8];
    __shared__ float s_mu, s_rstd;
    int row = blockIdx.x, tid = threadIdx.x;
    float4 v = *(const float4*)&s[row*DMOD + tid*4];
    float sum = v.x + v.y + v.z + v.w;
    float ssq = v.x*v.x + v.y*v.y + v.z*v.z + v.w*v.w;
    #pragma unroll
    for (int o = 16; o; o >>= 1) {
        sum += __shfl_xor_sync(0xffffffffu, sum, o);
        ssq += __shfl_xor_sync(0xffffffffu, ssq, o);
    }
    int lane = tid & 31, wid = tid >> 5;
    if (lane == 0) { sred[wid] = sum; sred[4 + wid] = ssq; }
    __syncthreads();
    if (tid == 0) {
        float a = sred[0]+sred[1]+sred[2]+sred[3];
        float q = sred[4]+sred[5]+sred[6]+sred[7];
        float mu = a * (1.f/DMOD);
        float var = q * (1.f/DMOD) - mu*mu;
        s_mu = mu; s_rstd = rsqrtf(var + 1e-5f);
    }
    __syncthreads();
    float mu = s_mu, rstd = s_rstd;
    float4 wv = *(const float4*)&w[tid*4];
    float4 bv = *(const float4*)&b[tid*4];
    float o4[4];
    o4[0] = (v.x-mu)*rstd*wv.x + bv.x;
    o4[1] = (v.y-mu)*rstd*wv.y + bv.y;
    o4[2] = (v.z-mu)*rstd*wv.z + bv.z;
    o4[3] = (v.w-mu)*rstd*wv.w + bv.w;
    union { bf16 h[4]; uint2 u; } H, L;
    #pragma unroll
    for (int j = 0; j < 4; j++) {
        H.h[j] = __float2bfloat16(o4[j]);
        L.h[j] = __float2bfloat16(o4[j] - __bfloat162float(H.h[j]));
    }
    int idx = row*DMOD + tid*4;
    *(uint2*)&g_sa_hi[idx] = H.u;
    *(uint2*)&g_sa_lo[idx] = L.u;
}

__global__ void wtrans_kernel(const float* __restrict__ Wq, const float* __restrict__ Wk,
                              const float* __restrict__ Wv, const float* __restrict__ Wg,
                              const float* __restrict__ Wo)
{
    __shared__ float t[32][33];
    int g = blockIdx.z;
    const float* W = (g==0)?Wq:(g==1)?Wk:(g==2)?Wv:(g==3)?Wg:Wo;
    int tx = threadIdx.x, ty = threadIdx.y;
    int bx = blockIdx.x*32, by = blockIdx.y*32;
    #pragma unroll
    for (int i = 0; i < 4; i++)
        t[ty + 8*i][tx] = W[(size_t)(by + ty + 8*i)*DMOD + bx + tx];
    __syncthreads();
    size_t base = (size_t)g*DMOD*DMOD;
    #pragma unroll
    for (int i = 0; i < 4; i++) {
        int n = bx + ty + 8*i, k = by + tx;
        float v = t[tx][ty + 8*i];
        bf16 h = __float2bfloat16(v);
        g_wt_hi[base + (size_t)n*DMOD + k] = h;
        g_wt_lo[base + (size_t)n*DMOD + k] = __float2bfloat16(v - __bfloat162float(h));
    }
}

__global__ __launch_bounds__(256) void conv_o_kernel()
{
    int idx = (blockIdx.x*256 + threadIdx.x)*4;
    float4 o = *(const float4*)&g_o[idx];
    float4 g = *(const float4*)&g_gate[idx];
    float v[4] = {o.x*g.x, o.y*g.y, o.z*g.z, o.w*g.w};
    union { bf16 h[4]; uint2 u; } H, L;
    #pragma unroll
    for (int j = 0; j < 4; j++) {
        H.h[j] = __float2bfloat16(v[j]);
        L.h[j] = __float2bfloat16(v[j] - __bfloat162float(H.h[j]));
    }
    *(uint2*)&g_oa_hi[idx] = H.u;
    *(uint2*)&g_oa_lo[idx] = L.u;
}

// WMMA bf16-split GEMM with 2-stage cp.async pipeline.
// modes 0-2 now emit q/k/v as bf16 hi/lo pairs for the WMMA flash kernel.
__global__ __launch_bounds__(256) void tc_gemm(const float* __restrict__ bq,
                                               float* __restrict__ Cout, int mode_sel)
{
    extern __shared__ __align__(16) char dynsm[];
    const int STAGE = 64*72*2;
    float* Cs = (float*)dynsm;

    int mode = (mode_sel < 0) ? (int)blockIdx.z : mode_sel;
    const bf16* Ah = (mode==4) ? g_oa_hi : g_sa_hi;
    const bf16* Al = (mode==4) ? g_oa_lo : g_sa_lo;
    size_t wb = (size_t)((mode==4)?4:mode)*DMOD*DMOD;
    const bf16* Bh = g_wt_hi + wb;
    const bf16* Bl = g_wt_lo + wb;

    int tid = threadIdx.x;
    int w = tid >> 5, wr = w >> 1, wc = w & 1;
    int m0 = blockIdx.y*64, n0 = blockIdx.x*64;
    int lrow = tid >> 2, lseg = (tid & 3) << 4;

    wmma::fragment<wmma::accumulator,16,16,16,float> acc[2];
    wmma::fill_fragment(acc[0], 0.f);
    wmma::fill_fragment(acc[1], 0.f);

    const bf16* gAh = Ah + (size_t)(m0+lrow)*DMOD + lseg;
    const bf16* gAl = Al + (size_t)(m0+lrow)*DMOD + lseg;
    const bf16* gBh = Bh + (size_t)(n0+lrow)*DMOD + lseg;
    const bf16* gBl = Bl + (size_t)(n0+lrow)*DMOD + lseg;
    int soff = (lrow*72 + lseg)*2;

    auto issue = [&](int ch, int st) {
        char* base = dynsm + st*4*STAGE;
        cp16(base + 0*STAGE + soff,      gAh + ch*64);
        cp16(base + 0*STAGE + soff + 16, gAh + ch*64 + 8);
        cp16(base + 1*STAGE + soff,      gAl + ch*64);
        cp16(base + 1*STAGE + soff + 16, gAl + ch*64 + 8);
        cp16(base + 2*STAGE + soff,      gBh + ch*64);
        cp16(base + 2*STAGE + soff + 16, gBh + ch*64 + 8);
        cp16(base + 3*STAGE + soff,      gBl + ch*64);
        cp16(base + 3*STAGE + soff + 16, gBl + ch*64 + 8);
        cp_commit();
    };

    issue(0, 0);
    for (int ch = 0; ch < 8; ch++) {
        int st = ch & 1;
        if (ch < 7) issue(ch+1, st^1);
        if (ch < 7) asm volatile("cp.async.wait_group 1;" ::: "memory");
        else        asm volatile("cp.async.wait_group 0;" ::: "memory");
        __syncthreads();
        bf16* Ah_s = (bf16*)(dynsm + st*4*STAGE + 0*STAGE);
        bf16* Al_s = (bf16*)(dynsm + st*4*STAGE + 1*STAGE);
        bf16* Bh_s = (bf16*)(dynsm + st*4*STAGE + 2*STAGE);
        bf16* Bl_s = (bf16*)(dynsm + st*4*STAGE + 3*STAGE);
        #pragma unroll
        for (int ks = 0; ks < 4; ks++) {
            wmma::fragment<wmma::matrix_a,16,16,16,bf16,wmma::row_major> fah, fal;
            wmma::load_matrix_sync(fah, Ah_s + (wr*16)*72 + ks*16, 72);
            wmma::load_matrix_sync(fal, Al_s + (wr*16)*72 + ks*16, 72);
            #pragma unroll
            for (int c = 0; c < 2; c++) {
                wmma::fragment<wmma::matrix_b,16,16,16,bf16,wmma::col_major> fbh, fbl;
                wmma::load_matrix_sync(fbh, Bh_s + (wc*32 + c*16)*72 + ks*16, 72);
                wmma::load_matrix_sync(fbl, Bl_s + (wc*32 + c*16)*72 + ks*16, 72);
                wmma::mma_sync(acc[c], fah, fbh, acc[c]);
                wmma::mma_sync(acc[c], fah, fbl, acc[c]);
                wmma::mma_sync(acc[c], fal, fbh, acc[c]);
            }
        }
        __syncthreads();
    }
    wmma::store_matrix_sync(Cs + (wr*16)*72 + wc*32,      acc[0], 72, wmma::mem_row_major);
    wmma::store_matrix_sync(Cs + (wr*16)*72 + wc*32 + 16, acc[1], 72, wmma::mem_row_major);
    __syncthreads();

    int r = lrow;
    int colg = n0 + lseg;
    if (mode <= 2) {
        bf16* dh = (mode==0) ? g_qh : (mode==1 ? g_kh : g_vh);
        bf16* dl = (mode==0) ? g_ql : (mode==1 ? g_kl : g_vl);
        size_t base = ((size_t)(colg >> 5)*NSEQ + m0 + r)*HDIM + (colg & 31);
        #pragma unroll
        for (int j = 0; j < 4; j++) {
            float4 v = *(float4*)&Cs[r*72 + lseg + j*4];
            if (mode == 0) {
                float4 bb = *(const float4*)&bq[colg + j*4];
                v.x = (v.x + bb.x)*QSCALE; v.y = (v.y + bb.y)*QSCALE;
                v.z = (v.z + bb.z)*QSCALE; v.w = (v.w + bb.w)*QSCALE;
            }
            float vr[4] = {v.x, v.y, v.z, v.w};
            union { bf16 h[4]; uint2 u; } H, L;
            #pragma unroll
            for (int e = 0; e < 4; e++) {
                H.h[e] = __float2bfloat16(vr[e]);
                L.h[e] = __float2bfloat16(vr[e] - __bfloat162float(H.h[e]));
            }
            *(uint2*)&dh[base + j*4] = H.u;
            *(uint2*)&dl[base + j*4] = L.u;
        }
    } else if (mode == 3) {
        float* dp = &g_gate[(size_t)(m0 + r)*DMOD + colg];
        #pragma unroll
        for (int j = 0; j < 4; j++) {
            float4 v = *(float4*)&Cs[r*72 + lseg + j*4];
            v.x = 1.f/(1.f + __expf(-v.x)); v.y = 1.f/(1.f + __expf(-v.y));
            v.z = 1.f/(1.f + __expf(-v.z)); v.w = 1.f/(1.f + __expf(-v.w));
            *(float4*)&dp[j*4] = v;
        }
    } else {
        float* dp = &Cout[(size_t)(m0 + r)*DMOD + colg];
        #pragma unroll
        for (int j = 0; j < 4; j++)
            *(float4*)&dp[j*4] = *(float4*)&Cs[r*72 + lseg + j*4];
    }
}

// fused LN(z)@Wz on tensor cores (R10 version, measured-best ~147us).
__global__ __launch_bounds__(256) void zbias_kernel(const float* __restrict__ z)
{
    __shared__ __align__(16) bf16 wzh[DZ][16];
    __shared__ __align__(16) bf16 wzl[DZ][16];
    __shared__ __align__(16) bf16 ztile[8][2][32][40];
    int tid = threadIdx.x, lane = tid & 31, w = tid >> 5;

    for (int i = tid; i < DZ*NHEAD; i += 256) {
        float v = g_wzp[i];
        bf16 h = __float2bfloat16(v);
        wzh[i >> 4][i & 15] = h;
        wzl[i >> 4][i & 15] = __float2bfloat16(v - __bfloat162float(h));
    }
    __syncthreads();

    int row0w = blockIdx.x*256 + w*32;
    const float* zwarp = z + (size_t)row0w*DZ;
    int lr8 = lane >> 3, lc8 = (lane & 7) << 2;

    wmma::fragment<wmma::accumulator,16,16,16,float> acc[2];
    wmma::fill_fragment(acc[0], 0.f);
    wmma::fill_fragment(acc[1], 0.f);
    float sumj[8], ssqj[8];
    #pragma unroll
    for (int j = 0; j < 8; j++) { sumj[j] = 0.f; ssqj[j] = 0.f; }

    bf16 (*zh)[40] = ztile[w][0];
    bf16 (*zl)[40] = ztile[w][1];

    float4 cur[8];
    #pragma unroll
    for (int j = 0; j < 8; j++)
        cur[j] = *(const float4*)&zwarp[(size_t)(j*4 + lr8)*DZ + lc8];

    for (int ch = 0; ch < 4; ch++) {
        #pragma unroll
        for (int j = 0; j < 8; j++) {
            float vr[4] = {cur[j].x, cur[j].y, cur[j].z, cur[j].w};
            union { bf16 h[4]; uint2 u; } H, L;
            #pragma unroll
            for (int e = 0; e < 4; e++) {
                H.h[e] = __float2bfloat16(vr[e]);
                L.h[e] = __float2bfloat16(vr[e] - __bfloat162float(H.h[e]));
                sumj[j] += vr[e];
                ssqj[j] = fmaf(vr[e], vr[e], ssqj[j]);
            }
            *(uint2*)&zh[j*4 + lr8][lc8] = H.u;
            *(uint2*)&zl[j*4 + lr8][lc8] = L.u;
        }
        __syncwarp();
        if (ch < 3) {
            #pragma unroll
            for (int j = 0; j < 8; j++)
                cur[j] = *(const float4*)&zwarp[(size_t)(j*4 + lr8)*DZ + (ch+1)*32 + lc8];
        }
        #pragma unroll
        for (int kt = 0; kt < 2; kt++) {
            wmma::fragment<wmma::matrix_b,16,16,16,bf16,wmma::row_major> fbh, fbl;
            wmma::load_matrix_sync(fbh, &wzh[ch*32 + kt*16][0], 16);
            wmma::load_matrix_sync(fbl, &wzl[ch*32 + kt*16][0], 16);
            #pragma unroll
            for (int rt = 0; rt < 2; rt++) {
                wmma::fragment<wmma::matrix_a,16,16,16,bf16,wmma::row_major> fah, fal;
                wmma::load_matrix_sync(fah, &zh[rt*16][kt*16], 40);
                wmma::load_matrix_sync(fal, &zl[rt*16][kt*16], 40);
                wmma::mma_sync(acc[rt], fah, fbh, acc[rt]);
                wmma::mma_sync(acc[rt], fah, fbl, acc[rt]);
                wmma::mma_sync(acc[rt], fal, fbh, acc[rt]);
            }
        }
        __syncwarp();
    }

    #pragma unroll
    for (int j = 0; j < 8; j++) {
        #pragma unroll
        for (int o = 1; o < 8; o <<= 1) {
            sumj[j] += __shfl_xor_sync(0xffffffffu, sumj[j], o);
            ssqj[j] += __shfl_xor_sync(0xffffffffu, ssqj[j], o);
        }
    }
    int srcLane = (lane & 3) * 8;
    float sum_own = 0.f, ssq_own = 0.f;
    #pragma unroll
    for (int j = 0; j < 8; j++) {
        float s_ = __shfl_sync(0xffffffffu, sumj[j], srcLane);
        float q_ = __shfl_sync(0xffffffffu, ssqj[j], srcLane);
        if ((lane >> 2) == j) { sum_own = s_; ssq_own = q_; }
    }

    float* Cs = (float*)ztile[w];
    wmma::store_matrix_sync(Cs,          acc[0], 20, wmma::mem_row_major);
    wmma::store_matrix_sync(Cs + 16*20,  acc[1], 20, wmma::mem_row_major);
    __syncwarp();

    float mu = sum_own * (1.f/DZ);
    float var = ssq_own * (1.f/DZ) - mu*mu;
    float rstd = rsqrtf(var + 1e-5f);
    int row = row0w + lane;
    #pragma unroll
    for (int h = 0; h < NHEAD; h++) {
        float a = Cs[lane*20 + h];
        g_scores[(size_t)h*NN + row] = rstd*(a - mu*g_alpha[h]) + g_beta[h];
    }
}

// Flash attention v2 on tensor cores. CTA = (64 q-rows, head), 8 warps.
// S = QK^T (bf16 3-way split) -> smem fp32; fp32 online softmax (4 lanes/row,
// m/l in regs); P split bf16 -> P@V WMMA -> partial in smem; O (smem fp32)
// updated by row-owning threads: O = O*c + part. 76800 B smem -> 2 CTA/SM.
__global__ __launch_bounds__(256) void flash_kernel()
{
    extern __shared__ __align__(16) char fsm[];
    bf16* Qh = (bf16*)fsm;                 // [64][40]
    bf16* Ql = Qh + 64*40;
    bf16* Kh = Ql + 64*40;
    bf16* Kl = Kh + 64*40;
    bf16* Vh = Kl + 64*40;
    bf16* Vl = Vh + 64*40;                 // 30720 B
    float* S  = (float*)(fsm + 30720);     // [64][72] fp32 (also PV partial)
    bf16* Ph = (bf16*)(fsm + 49152);       // [64][72]
    bf16* Pl = Ph + 64*72;                 // -> 67584
    float* Ob = (float*)(fsm + 67584);     // [64][36] -> 76800

    int tid = threadIdx.x, w = tid >> 5;
    int h = blockIdx.y, q0 = blockIdx.x*64;
    size_t hb = (size_t)h*NSEQ*HDIM;
    const float* zp = g_scores + (size_t)h*NN;

    int row = tid >> 2;
    int seg8 = (tid & 3) << 3;     // 8 bf16 = one uint4
    // load Q tiles
    *(uint4*)&Qh[row*40 + seg8] = *(const uint4*)&g_qh[hb + (size_t)(q0+row)*HDIM + seg8];
    *(uint4*)&Ql[row*40 + seg8] = *(const uint4*)&g_ql[hb + (size_t)(q0+row)*HDIM + seg8];
    for (int i = tid; i < 64*36; i += 256) Ob[i] = 0.f;

    float m = -1e30f, l = 0.f;
    int colb = (tid & 3) << 4;     // 16 softmax cols per thread
    int oc = (tid & 3) << 3;       // 8 O cols per thread

    for (int kb = 0; kb < NSEQ; kb += 64) {
        uint4 kh = *(const uint4*)&g_kh[hb + (size_t)(kb+row)*HDIM + seg8];
        uint4 kl = *(const uint4*)&g_kl[hb + (size_t)(kb+row)*HDIM + seg8];
        uint4 vh = *(const uint4*)&g_vh[hb + (size_t)(kb+row)*HDIM + seg8];
        uint4 vl = *(const uint4*)&g_vl[hb + (size_t)(kb+row)*HDIM + seg8];
        __syncthreads();                       // prev iter done with K/V/part
        *(uint4*)&Kh[row*40 + seg8] = kh;
        *(uint4*)&Kl[row*40 + seg8] = kl;
        *(uint4*)&Vh[row*40 + seg8] = vh;
        *(uint4*)&Vl[row*40 + seg8] = vl;
        __syncthreads();

        // S = QK^T : warp w -> row-tile (w>>1), col-tiles {w&1, (w&1)+2}
        {
            int mr = w >> 1;
            wmma::fragment<wmma::accumulator,16,16,16,float> sa[2];
            wmma::fill_fragment(sa[0], 0.f);
            wmma::fill_fragment(sa[1], 0.f);
            #pragma unroll
            for (int ks = 0; ks < 2; ks++) {
                wmma::fragment<wmma::matrix_a,16,16,16,bf16,wmma::row_major> qhf, qlf;
                wmma::load_matrix_sync(qhf, Qh + (mr*16)*40 + ks*16, 40);
                wmma::load_matrix_sync(qlf, Ql + (mr*16)*40 + ks*16, 40);
                #pragma unroll
                for (int c = 0; c < 2; c++) {
                    int nc = (w & 1) + c*2;
                    wmma::fragment<wmma::matrix_b,16,16,16,bf16,wmma::col_major> kbh, kbl;
                    wmma::load_matrix_sync(kbh, Kh + (nc*16)*40 + ks*16, 40);
                    wmma::load_matrix_sync(kbl, Kl + (nc*16)*40 + ks*16, 40);
                    wmma::mma_sync(sa[c], qhf, kbh, sa[c]);
                    wmma::mma_sync(sa[c], qhf, kbl, sa[c]);
                    wmma::mma_sync(sa[c], qlf, kbh, sa[c]);
                }
            }
            wmma::store_matrix_sync(S + (mr*16)*72 + (w&1)*16,       sa[0], 72, wmma::mem_row_major);
            wmma::store_matrix_sync(S + (mr*16)*72 + ((w&1)+2)*16,   sa[1], 72, wmma::mem_row_major);
        }
        __syncthreads();

        // softmax: thread owns row, cols [colb, colb+16)
        float sv[16];
        #pragma unroll
        for (int j = 0; j < 4; j++) {
            float4 s4 = *(float4*)&S[row*72 + colb + j*4];
            float4 z4 = *(const float4*)&zp[(size_t)(q0+row)*NSEQ + kb + colb + j*4];
            sv[j*4+0] = s4.x + z4.x; sv[j*4+1] = s4.y + z4.y;
            sv[j*4+2] = s4.z + z4.z; sv[j*4+3] = s4.w + z4.w;
        }
        float mx = sv[0];
        #pragma unroll
        for (int j = 1; j < 16; j++) mx = fmaxf(mx, sv[j]);
        mx = fmaxf(mx, __shfl_xor_sync(0xffffffffu, mx, 1));
        mx = fmaxf(mx, __shfl_xor_sync(0xffffffffu, mx, 2));
        float mnew = fmaxf(m, mx);
        float c = __expf(m - mnew);
        float rs = 0.f;
        union { bf16 h[8]; uint4 u; } PH[2], PL[2];
        #pragma unroll
        for (int j = 0; j < 16; j++) {
            float e = __expf(sv[j] - mnew);
            rs += e;
            bf16 eh = __float2bfloat16(e);
            PH[j>>3].h[j&7] = eh;
            PL[j>>3].h[j&7] = __float2bfloat16(e - __bfloat162float(eh));
        }
        rs += __shfl_xor_sync(0xffffffffu, rs, 1);
        rs += __shfl_xor_sync(0xffffffffu, rs, 2);
        l = l*c + rs;
        m = mnew;
        *(uint4*)&Ph[row*72 + colb]     = PH[0].u;
        *(uint4*)&Ph[row*72 + colb + 8] = PH[1].u;
        *(uint4*)&Pl[row*72 + colb]     = PL[0].u;
        *(uint4*)&Pl[row*72 + colb + 8] = PL[1].u;
        __syncthreads();

        // P@V : 8 subtiles (4 row x 2 col), warp w -> (w>>1, w&1); partial into S
        {
            int mr = w >> 1, nc = w & 1;
            wmma::fragment<wmma::accumulator,16,16,16,float> oa;
            wmma::fill_fragment(oa, 0.f);
            #pragma unroll
            for (int ks = 0; ks < 4; ks++) {
                wmma::fragment<wmma::matrix_a,16,16,16,bf16,wmma::row_major> phf, plf;
                wmma::load_matrix_sync(phf, Ph + (mr*16)*72 + ks*16, 72);
                wmma::load_matrix_sync(plf, Pl + (mr*16)*72 + ks*16, 72);
                wmma::fragment<wmma::matrix_b,16,16,16,bf16,wmma::row_major> vbh, vbl;
                wmma::load_matrix_sync(vbh, Vh + (ks*16)*40 + nc*16, 40);
                wmma::load_matrix_sync(vbl, Vl + (ks*16)*40 + nc*16, 40);
                wmma::mma_sync(oa, phf, vbh, oa);
                wmma::mma_sync(oa, phf, vbl, oa);
                wmma::mma_sync(oa, plf, vbh, oa);
            }
            wmma::store_matrix_sync(S + (mr*16)*72 + nc*16, oa, 72, wmma::mem_row_major);
        }
        __syncthreads();

        // O = O*c + part
        #pragma unroll
        for (int j = 0; j < 2; j++) {
            float4 p = *(float4*)&S[row*72 + oc + j*4];
            float4 o = *(float4*)&Ob[row*36 + oc + j*4];
            o.x = o.x*c + p.x; o.y = o.y*c + p.y;
            o.z = o.z*c + p.z; o.w = o.w*c + p.w;
            *(float4*)&Ob[row*36 + oc + j*4] = o;
        }
    }

    float inv = 1.f / l;
    #pragma unroll
    for (int j = 0; j < 2; j++) {
        float4 o = *(float4*)&Ob[row*36 + oc + j*4];
        o.x *= inv; o.y *= inv; o.z *= inv; o.w *= inv;
        *(float4*)&g_o[(size_t)(q0+row)*DMOD + h*HDIM + oc + j*4] = o;
    }
}

extern "C" void kernel_launch(void* const* d_in, const int* in_sizes, int n_in,
                              void* d_out, int out_size)
{
    const float* s   = (const float*)d_in[0];
    const float* z   = (const float*)d_in[1];
    const float* nsw = (const float*)d_in[2];
    const float* nsb = (const float*)d_in[3];
    const float* Wq  = (const float*)d_in[4];
    const float* bq  = (const float*)d_in[5];
    const float* Wk  = (const float*)d_in[6];
    const float* Wv  = (const float*)d_in[7];
    const float* Wg  = (const float*)d_in[8];
    const float* zw  = (const float*)d_in[9];
    const float* zb  = (const float*)d_in[10];
    const float* Wz  = (const float*)d_in[11];
    const float* Wo  = (const float*)d_in[12];
    float* out = (float*)d_out;

    cudaFuncSetAttribute(tc_gemm, cudaFuncAttributeMaxDynamicSharedMemorySize, 73728);
    cudaFuncSetAttribute(flash_kernel, cudaFuncAttributeMaxDynamicSharedMemorySize, 76800);

    prep_kernel<<<1, 256>>>(Wz, zw, zb);
    ln_s_kernel<<<NSEQ, 128>>>(s, nsw, nsb);
    wtrans_kernel<<<dim3(16,16,5), dim3(32,8)>>>(Wq, Wk, Wv, Wg, Wo);
    tc_gemm<<<dim3(8,16,4), 256, 73728>>>(bq, nullptr, -1);
    zbias_kernel<<<NN/256, 256>>>(z);
    flash_kernel<<<dim3(NSEQ/64, NHEAD), 256, 76800>>>();
    conv_o_kernel<<<NSEQ*DMOD/4/256, 256>>>();
    tc_gemm<<<dim3(8,16,1), 256, 73728>>>(bq, out, 4);
}